// round 6
// baseline (speedup 1.0000x reference)
#include <cuda_runtime.h>
#include <cuda_bf16.h>
#include <math.h>
#include <stdint.h>

// ---------------------------------------------------------------------------
// Problem constants
// ---------------------------------------------------------------------------
#define BATCH 8
#define CIN   256
#define EMB   512
#define HW    48
#define NPIX  2304
#define KDIM  2304

// ---------------------------------------------------------------------------
// Scratch: split hi/lo bf16 planes. ~297 MB total.
//  col planes aliased by fp32 att (softmax packs u32 in place).
//  qHi+qLo region aliased by fp32 outT (q dead after logits).
// ---------------------------------------------------------------------------
#define CBYT ((size_t)BATCH * NPIX * KDIM * 2)   // one col plane
#define WBYT ((size_t)EMB * KDIM * 2)
#define QBYT ((size_t)BATCH * NPIX * EMB * 2)

#define OFF_COLH ((size_t)0)
#define OFF_COLL (CBYT)
#define OFF_WQH  (2 * CBYT)
#define OFF_WQL  (OFF_WQH + WBYT)
#define OFF_WKH  (OFF_WQL + WBYT)
#define OFF_WKL  (OFF_WKH + WBYT)
#define OFF_WVH  (OFF_WKL + WBYT)
#define OFF_WVL  (OFF_WVH + WBYT)
#define OFF_QH   (OFF_WVL + WBYT)
#define OFF_QL   (OFF_QH + QBYT)
#define OFF_KH   (OFF_QL + QBYT)
#define OFF_KL   (OFF_KH + QBYT)
#define OFF_VH   (OFF_KL + QBYT)
#define OFF_VL   (OFF_VH + QBYT)
#define SCRATCH_BYTES (OFF_VL + QBYT)

__device__ __align__(1024) unsigned char g_scratch[SCRATCH_BYTES];

// ---------------------------------------------------------------------------
// Helpers
// ---------------------------------------------------------------------------
__device__ __forceinline__ uint32_t smem_u32(const void* p) {
    uint32_t a;
    asm("{ .reg .u64 t; cvta.to.shared.u64 t, %1; cvt.u32.u64 %0, t; }"
        : "=r"(a) : "l"(p));
    return a;
}

// SW64 swizzle: 16B column bits [4:6) ^= row bits (offset bits [7:9))
#define SWZ64(o) ((o) ^ (((o) >> 3) & 0x30))

__device__ __forceinline__ uint32_t pack_split(float x) {
    __nv_bfloat16 h = __float2bfloat16(x);
    float hf = __bfloat162float(h);
    __nv_bfloat16 l = __float2bfloat16(x - hf);
    return ((uint32_t)__bfloat16_as_ushort(h) << 16) | (uint32_t)__bfloat16_as_ushort(l);
}
__device__ __forceinline__ void split2(float x0, float x1, uint32_t& hi, uint32_t& lo) {
    __nv_bfloat16 h0 = __float2bfloat16(x0), h1 = __float2bfloat16(x1);
    __nv_bfloat16 l0 = __float2bfloat16(x0 - __bfloat162float(h0));
    __nv_bfloat16 l1 = __float2bfloat16(x1 - __bfloat162float(h1));
    hi = (uint32_t)__bfloat16_as_ushort(h0) | ((uint32_t)__bfloat16_as_ushort(h1) << 16);
    lo = (uint32_t)__bfloat16_as_ushort(l0) | ((uint32_t)__bfloat16_as_ushort(l1) << 16);
}

__device__ __forceinline__ void ldsm4(uint32_t& r0, uint32_t& r1, uint32_t& r2,
                                      uint32_t& r3, uint32_t addr) {
    asm volatile("ldmatrix.sync.aligned.m8n8.x4.shared.b16 {%0,%1,%2,%3}, [%4];"
                 : "=r"(r0), "=r"(r1), "=r"(r2), "=r"(r3) : "r"(addr));
}
__device__ __forceinline__ void mma16816(float* d, const uint32_t* a,
                                         const uint32_t* b) {
    asm volatile(
        "mma.sync.aligned.m16n8k16.row.col.f32.bf16.bf16.f32 "
        "{%0,%1,%2,%3},{%4,%5,%6,%7},{%8,%9},{%0,%1,%2,%3};"
        : "+f"(d[0]), "+f"(d[1]), "+f"(d[2]), "+f"(d[3])
        : "r"(a[0]), "r"(a[1]), "r"(a[2]), "r"(a[3]), "r"(b[0]), "r"(b[1]));
}
__device__ __forceinline__ void cp16(uint32_t s, const void* g) {
    asm volatile("cp.async.cg.shared.global [%0], [%1], 16;"
                 :: "r"(s), "l"(g) : "memory");
}
#define CP_COMMIT asm volatile("cp.async.commit_group;" ::: "memory")
#define CP_WAIT1  asm volatile("cp.async.wait_group 1;" ::: "memory")

__device__ __forceinline__ void sts64b(uint32_t addr, uint32_t lo, uint32_t hi) {
    unsigned long long v = ((unsigned long long)hi << 32) | lo;
    asm volatile("st.shared.b64 [%0], %1;" :: "r"(addr), "l"(v) : "memory");
}

// ---------------------------------------------------------------------------
// Converters
// ---------------------------------------------------------------------------
__global__ void pack_weights(const float* __restrict__ Wq, const float* __restrict__ Wk,
                             const float* __restrict__ Wv,
                             __nv_bfloat16* __restrict__ qh, __nv_bfloat16* __restrict__ ql,
                             __nv_bfloat16* __restrict__ kh, __nv_bfloat16* __restrict__ kl,
                             __nv_bfloat16* __restrict__ vh, __nv_bfloat16* __restrict__ vl)
{
    long i = (long)blockIdx.x * 256 + threadIdx.x;
    const long n = (long)EMB * KDIM;
    if (i >= n) return;
    float a = Wq[i], b = Wk[i], c = Wv[i];
    __nv_bfloat16 h;
    h = __float2bfloat16(a); qh[i] = h; ql[i] = __float2bfloat16(a - __bfloat162float(h));
    h = __float2bfloat16(b); kh[i] = h; kl[i] = __float2bfloat16(b - __bfloat162float(h));
    h = __float2bfloat16(c); vh[i] = h; vl[i] = __float2bfloat16(c - __bfloat162float(h));
}

__global__ void build_col(const float* __restrict__ feat,
                          __nv_bfloat16* __restrict__ cH, __nv_bfloat16* __restrict__ cL)
{
    long idx = (long)blockIdx.x * 256 + threadIdx.x;
    const long total = (long)BATCH * NPIX * KDIM;
    if (idx >= total) return;
    int k = (int)(idx % KDIM);
    long t = idx / KDIM;
    int n = (int)(t % NPIX);
    int b = (int)(t / NPIX);
    int c = k / 9, k9 = k - 9 * c;
    int ky = k9 / 3, kx = k9 - 3 * ky;
    int h = n / HW, w = n - HW * h;
    int hs = h + ky - 1, ws = w + kx - 1;
    float v = 0.f;
    if (hs >= 0 && hs < HW && ws >= 0 && ws < HW)
        v = feat[(((long)b * CIN + c) * HW + hs) * HW + ws];
    __nv_bfloat16 hh = __float2bfloat16(v);
    cH[idx] = hh;
    cL[idx] = __float2bfloat16(v - __bfloat162float(hh));
}

// ---------------------------------------------------------------------------
// GEMM: D[m][n] = sum_k A[m][k]*B[n][k], split-bf16 3-MMA, fp32 accum.
// CTA 128x256, 8 warps (2x4) of 64x64. KC=32, 3-stage cp.async pipeline.
// Stage layout: Ah[0,8K) Al[8K,16K) Bh[16K,32K) Bl[32K,48K).
// modes: 0 logits fp32 | 1 q/k conv (bias[n], plane out, z&1 sel)
//        2 v conv (bias[m], plane out) | 3 output (A packed u32, fp32 out)
// ---------------------------------------------------------------------------
#define KC    32
#define NST   3
#define STG   49152
#define SMEM_TOTAL (NST * STG)

__global__ __launch_bounds__(256, 1)
void gemm_mma(const __nv_bfloat16* __restrict__ aHi, const __nv_bfloat16* __restrict__ aLo,
              const uint32_t* __restrict__ aPk, long sA, int lda,
              const __nv_bfloat16* __restrict__ bHi0, const __nv_bfloat16* __restrict__ bLo0,
              const __nv_bfloat16* __restrict__ bHi1, const __nv_bfloat16* __restrict__ bLo1,
              long sB, int ldb,
              int K, int mode,
              float* __restrict__ Cf, long sCf, int ldc,
              __nv_bfloat16* __restrict__ pH0, __nv_bfloat16* __restrict__ pL0,
              __nv_bfloat16* __restrict__ pH1, __nv_bfloat16* __restrict__ pL1,
              long sCp, int ldcp,
              const float* __restrict__ bias0, const float* __restrict__ bias1)
{
    extern __shared__ __align__(128) unsigned char smem[];
    const uint32_t sbase = smem_u32(smem);
    const int tid = threadIdx.x, lid = tid & 31, wid = tid >> 5;
    const int warp_m = wid >> 2, warp_n = wid & 3;

    int bz = blockIdx.z, b, wsel = 0;
    if (mode == 1) { b = bz >> 1; wsel = bz & 1; } else { b = bz; }
    const int bm = blockIdx.y * 128, bn = blockIdx.x * 256;

    // ---- B loader mapping: 8 cp.async per thread per chunk ----
    const __nv_bfloat16* BH = (mode == 1 && wsel) ? bHi1 : bHi0;
    const __nv_bfloat16* BL = (mode == 1 && wsel) ? bLo1 : bLo0;
    const __nv_bfloat16* bg[8]; uint32_t bs_[8];
#pragma unroll
    for (int i = 0; i < 8; i++) {
        int o = tid + 256 * i; int pl = o >> 10; int r = (o >> 2) & 255; int c = o & 3;
        bg[i] = (pl ? BL : BH) + (long)b * sB + (long)(bn + r) * ldb + c * 8;
        bs_[i] = 16384u + (uint32_t)pl * 16384u + SWZ64((uint32_t)(r * 64 + c * 16));
    }
    // ---- A loader mapping ----
    const __nv_bfloat16* ag[4]; uint32_t as_[4];
    const uint32_t* apg[4]; uint32_t ash[4];
    if (mode != 3) {
#pragma unroll
        for (int i = 0; i < 4; i++) {
            int o = tid + 256 * i; int pl = o >> 9; int r = (o >> 2) & 127; int c = o & 3;
            ag[i] = (pl ? aLo : aHi) + (long)b * sA + (long)(bm + r) * lda + c * 8;
            as_[i] = (uint32_t)pl * 8192u + SWZ64((uint32_t)(r * 64 + c * 16));
        }
    } else {
#pragma unroll
        for (int i = 0; i < 4; i++) {
            int o = tid + 256 * i; int r = o >> 3; int seg = o & 7;
            apg[i] = aPk + (long)b * sA + (long)(bm + r) * lda + seg * 4;
            ash[i] = SWZ64((uint32_t)(r * 64 + seg * 8));
        }
    }

#define ISSUE_B(c, st) do { uint32_t _bb = sbase + (uint32_t)(st) * STG;        \
        _Pragma("unroll") for (int _i = 0; _i < 8; _i++)                        \
            cp16(_bb + bs_[_i], bg[_i] + (long)(c) * KC); } while (0)
#define ISSUE_A(c, st) do { uint32_t _ab = sbase + (uint32_t)(st) * STG;        \
        _Pragma("unroll") for (int _i = 0; _i < 4; _i++)                        \
            cp16(_ab + as_[_i], ag[_i] + (long)(c) * KC); } while (0)
#define LDG_A3(c) do { _Pragma("unroll") for (int _i = 0; _i < 4; _i++)         \
            rga[_i] = *(const uint4*)(apg[_i] + (long)(c) * KC); } while (0)
#define STS_A3(st) do { uint32_t _ab = sbase + (uint32_t)(st) * STG;            \
        _Pragma("unroll") for (int _i = 0; _i < 4; _i++) {                      \
            sts64b(_ab + ash[_i],                                               \
                   __byte_perm(rga[_i].x, rga[_i].y, 0x7632),                   \
                   __byte_perm(rga[_i].z, rga[_i].w, 0x7632));                  \
            sts64b(_ab + 8192 + ash[_i],                                        \
                   __byte_perm(rga[_i].x, rga[_i].y, 0x5410),                   \
                   __byte_perm(rga[_i].z, rga[_i].w, 0x5410)); } } while (0)

    float acc[4][8][4];
#pragma unroll
    for (int i = 0; i < 4; i++)
#pragma unroll
        for (int j = 0; j < 8; j++)
#pragma unroll
            for (int r = 0; r < 4; r++) acc[i][j][r] = 0.f;

    const int nchunk = K / KC;
    uint4 rga[4];

    // prologue: chunks 0,1
    if (mode != 3) ISSUE_A(0, 0); else { LDG_A3(0); STS_A3(0); }
    ISSUE_B(0, 0);
    CP_COMMIT;
    if (mode != 3) ISSUE_A(1, 1); else LDG_A3(1);   // mode3: hold chunk1 in regs
    ISSUE_B(1, 1);
    CP_COMMIT;

    const int sub = lid >> 3, l7 = lid & 7;
    const int arow = warp_m * 64 + (sub & 1) * 8 + l7;
    const int brow = warp_n * 64 + (sub >> 1) * 8 + l7;

    for (int c = 0; c < nchunk; c++) {
        CP_WAIT1;
        __syncthreads();

        const int cn = c + 2, st2 = cn % NST;
        if (mode == 3) {
            if (c + 1 < nchunk) STS_A3((c + 1) % NST);   // store held chunk c+1
            if (cn < nchunk) LDG_A3(cn);                 // fetch chunk c+2
        } else if (cn < nchunk) {
            ISSUE_A(cn, st2);
        }
        if (cn < nchunk) ISSUE_B(cn, st2);
        CP_COMMIT;

        const uint32_t stA  = sbase + (uint32_t)(c % NST) * STG;
        const uint32_t stBh = stA + 16384u, stBl = stA + 32768u;

#pragma unroll
        for (int ks = 0; ks < 2; ks++) {
            uint32_t ah[4][4], al[4][4];
            const int akb = ks * 16 + (sub >> 1) * 8;
#pragma unroll
            for (int i = 0; i < 4; i++) {
                const uint32_t off = SWZ64((uint32_t)((arow + i * 16) * 64 + akb * 2));
                ldsm4(ah[i][0], ah[i][1], ah[i][2], ah[i][3], stA + off);
                ldsm4(al[i][0], al[i][1], al[i][2], al[i][3], stA + 8192u + off);
            }
            const int bkb = ks * 16 + (sub & 1) * 8;
#pragma unroll
            for (int h = 0; h < 2; h++) {
                uint32_t bh[4][2], bl[4][2];
#pragma unroll
                for (int g2 = 0; g2 < 2; g2++) {
                    const int g = h * 2 + g2;
                    const uint32_t off = SWZ64((uint32_t)((brow + g * 16) * 64 + bkb * 2));
                    ldsm4(bh[2 * g2][0], bh[2 * g2][1], bh[2 * g2 + 1][0],
                          bh[2 * g2 + 1][1], stBh + off);
                    ldsm4(bl[2 * g2][0], bl[2 * g2][1], bl[2 * g2 + 1][0],
                          bl[2 * g2 + 1][1], stBl + off);
                }
#pragma unroll
                for (int i = 0; i < 4; i++)
#pragma unroll
                    for (int jj = 0; jj < 4; jj++) {
                        const int j = h * 4 + jj;
                        mma16816(acc[i][j], ah[i], bh[jj]);
                        mma16816(acc[i][j], ah[i], bl[jj]);
                        mma16816(acc[i][j], al[i], bh[jj]);
                    }
            }
        }
    }

    // ---- epilogue ----
    const float* bias = (mode == 1) ? (wsel ? bias1 : bias0) : bias0;
#pragma unroll
    for (int i = 0; i < 4; i++)
#pragma unroll
        for (int j = 0; j < 8; j++) {
            const int m = bm + warp_m * 64 + i * 16 + (lid >> 2);
            const int n = bn + warp_n * 64 + j * 8 + (lid & 3) * 2;
            const float d0 = acc[i][j][0], d1 = acc[i][j][1];
            const float d2 = acc[i][j][2], d3 = acc[i][j][3];
            if (mode == 0 || mode == 3) {
                float* bp = Cf + (long)b * sCf;
                *(float2*)(bp + (long)m * ldc + n)       = make_float2(d0, d1);
                *(float2*)(bp + (long)(m + 8) * ldc + n) = make_float2(d2, d3);
            } else if (mode == 1) {
                __nv_bfloat16* dH = (wsel ? pH1 : pH0) + (long)b * sCp;
                __nv_bfloat16* dL = (wsel ? pL1 : pL0) + (long)b * sCp;
                const float b0 = bias[n], b1 = bias[n + 1];
                uint32_t h, l;
                split2(d0 + b0, d1 + b1, h, l);
                *(uint32_t*)(dH + (long)m * ldcp + n) = h;
                *(uint32_t*)(dL + (long)m * ldcp + n) = l;
                split2(d2 + b0, d3 + b1, h, l);
                *(uint32_t*)(dH + (long)(m + 8) * ldcp + n) = h;
                *(uint32_t*)(dL + (long)(m + 8) * ldcp + n) = l;
            } else {
                __nv_bfloat16* dH = pH0 + (long)b * sCp;
                __nv_bfloat16* dL = pL0 + (long)b * sCp;
                const float bm0 = bias[m], bm8 = bias[m + 8];
                uint32_t h, l;
                split2(d0 + bm0, d1 + bm0, h, l);
                *(uint32_t*)(dH + (long)m * ldcp + n) = h;
                *(uint32_t*)(dL + (long)m * ldcp + n) = l;
                split2(d2 + bm8, d3 + bm8, h, l);
                *(uint32_t*)(dH + (long)(m + 8) * ldcp + n) = h;
                *(uint32_t*)(dL + (long)(m + 8) * ldcp + n) = l;
            }
        }
}

// ---------------------------------------------------------------------------
// Softmax over rows of att (fp32 in), writes packed split u32 IN PLACE.
// ---------------------------------------------------------------------------
__global__ __launch_bounds__(256)
void softmax_pack(float* __restrict__ att)
{
    const long row = blockIdx.x;
    float* p = att + row * NPIX;
    uint32_t* pu = (uint32_t*)p;
    __shared__ float red[256];
    const int t = threadIdx.x;

    float vals[9];
    float m = -INFINITY;
#pragma unroll
    for (int i = 0; i < 9; i++) {
        vals[i] = p[t + i * 256];
        m = fmaxf(m, vals[i]);
    }
    red[t] = m; __syncthreads();
    for (int s = 128; s > 0; s >>= 1) {
        if (t < s) red[t] = fmaxf(red[t], red[t + s]);
        __syncthreads();
    }
    m = red[0]; __syncthreads();

    float sum = 0.f;
#pragma unroll
    for (int i = 0; i < 9; i++) {
        vals[i] = __expf(vals[i] - m);
        sum += vals[i];
    }
    red[t] = sum; __syncthreads();
    for (int s = 128; s > 0; s >>= 1) {
        if (t < s) red[t] += red[t + s];
        __syncthreads();
    }
    const float inv = 1.f / red[0];
#pragma unroll
    for (int i = 0; i < 9; i++)
        pu[t + i * 256] = pack_split(vals[i] * inv);
}

// ---------------------------------------------------------------------------
// Final: out[b][e][n] = outT[b][n][e] + (vHi[b][e][n] + vLo[b][e][n])
// ---------------------------------------------------------------------------
__global__ void epilogue_kernel(const float* __restrict__ outT,
                                const __nv_bfloat16* __restrict__ vH,
                                const __nv_bfloat16* __restrict__ vL,
                                float* __restrict__ out)
{
    __shared__ float tile[32][33];
    const int b = blockIdx.z;
    const float* src = outT + (long)b * NPIX * EMB;   // [N][E]
    const __nv_bfloat16* vh = vH + (long)b * EMB * NPIX;
    const __nv_bfloat16* vl = vL + (long)b * EMB * NPIX;
    float* ob = out + (long)b * EMB * NPIX;
    const int e0 = blockIdx.x * 32;
    const int n0 = blockIdx.y * 32;
    const int tx = threadIdx.x, ty = threadIdx.y;     // 32 x 8
#pragma unroll
    for (int i = 0; i < 32; i += 8)
        tile[ty + i][tx] = src[(long)(n0 + ty + i) * EMB + (e0 + tx)];
    __syncthreads();
#pragma unroll
    for (int i = 0; i < 32; i += 8) {
        long o = (long)(e0 + ty + i) * NPIX + (n0 + tx);
        ob[o] = tile[tx][ty + i] + __bfloat162float(vh[o]) + __bfloat162float(vl[o]);
    }
}

// ---------------------------------------------------------------------------
// launch
// ---------------------------------------------------------------------------
extern "C" void kernel_launch(void* const* d_in, const int* in_sizes, int n_in,
                              void* d_out, int out_size)
{
    const float* feat = (const float*)d_in[0];
    const float* Wq   = (const float*)d_in[1];
    const float* bq   = (const float*)d_in[2];
    const float* Wk   = (const float*)d_in[3];
    const float* bk   = (const float*)d_in[4];
    const float* Wv   = (const float*)d_in[5];
    const float* bv   = (const float*)d_in[6];
    float* out = (float*)d_out;

    unsigned char* base;
    cudaGetSymbolAddress((void**)&base, g_scratch);
    __nv_bfloat16* colH = (__nv_bfloat16*)(base + OFF_COLH);
    __nv_bfloat16* colL = (__nv_bfloat16*)(base + OFF_COLL);
    __nv_bfloat16* wqH  = (__nv_bfloat16*)(base + OFF_WQH);
    __nv_bfloat16* wqL  = (__nv_bfloat16*)(base + OFF_WQL);
    __nv_bfloat16* wkH  = (__nv_bfloat16*)(base + OFF_WKH);
    __nv_bfloat16* wkL  = (__nv_bfloat16*)(base + OFF_WKL);
    __nv_bfloat16* wvH  = (__nv_bfloat16*)(base + OFF_WVH);
    __nv_bfloat16* wvL  = (__nv_bfloat16*)(base + OFF_WVL);
    __nv_bfloat16* qH   = (__nv_bfloat16*)(base + OFF_QH);
    __nv_bfloat16* qL   = (__nv_bfloat16*)(base + OFF_QL);
    __nv_bfloat16* kH   = (__nv_bfloat16*)(base + OFF_KH);
    __nv_bfloat16* kL   = (__nv_bfloat16*)(base + OFF_KL);
    __nv_bfloat16* vH   = (__nv_bfloat16*)(base + OFF_VH);
    __nv_bfloat16* vL   = (__nv_bfloat16*)(base + OFF_VL);
    float* att  = (float*)(base + OFF_COLH);   // alias; col planes dead by then
    float* outT = (float*)(base + OFF_QH);     // alias; q planes dead by then

    cudaFuncSetAttribute(gemm_mma, cudaFuncAttributeMaxDynamicSharedMemorySize,
                         SMEM_TOTAL);

    // 1) converters
    {
        long n = (long)EMB * KDIM;
        pack_weights<<<(unsigned)((n + 255) / 256), 256>>>(Wq, Wk, Wv,
                                                           wqH, wqL, wkH, wkL, wvH, wvL);
        long total = (long)BATCH * NPIX * KDIM;
        build_col<<<(unsigned)((total + 255) / 256), 256>>>(feat, colH, colL);
    }

    const long colS = (long)NPIX * KDIM;
    const long qtS  = (long)NPIX * EMB;
    const long attS = (long)NPIX * NPIX;

    // 2) q,k conv: D[n][e] = col[n][:] . W[e][:] + bias[e]
    {
        dim3 grid(EMB / 256, NPIX / 128, 2 * BATCH);
        gemm_mma<<<grid, 256, SMEM_TOTAL>>>(colH, colL, nullptr, colS, KDIM,
                                            wqH, wqL, wkH, wkL, 0, KDIM,
                                            KDIM, 1,
                                            nullptr, 0, 0,
                                            qH, qL, kH, kL, qtS, EMB,
                                            bq, bk);
    }
    // 3) v conv: D[e][n] = W[e][:] . col[n][:] + bias[e]
    {
        dim3 grid(NPIX / 256, EMB / 128, BATCH);
        gemm_mma<<<grid, 256, SMEM_TOTAL>>>(wvH, wvL, nullptr, 0, KDIM,
                                            colH, colL, nullptr, nullptr, colS, KDIM,
                                            KDIM, 2,
                                            nullptr, 0, 0,
                                            vH, vL, nullptr, nullptr, qtS, NPIX,
                                            bv, nullptr);
    }
    // 4) logits: att[i][j] = q[i][:] . k[j][:]   (K=512)
    {
        dim3 grid(NPIX / 256, NPIX / 128, BATCH);
        gemm_mma<<<grid, 256, SMEM_TOTAL>>>(qH, qL, nullptr, qtS, EMB,
                                            kH, kL, nullptr, nullptr, qtS, EMB,
                                            EMB, 0,
                                            att, attS, NPIX,
                                            nullptr, nullptr, nullptr, nullptr, 0, 0,
                                            nullptr, nullptr);
    }
    // 5) softmax rows + pack u32 in place
    softmax_pack<<<BATCH * NPIX, 256>>>(att);

    // 6) output: outT[i][e] = att[i][:] . v[e][:]  (K=2304; A packed)
    {
        dim3 grid(EMB / 256, NPIX / 128, BATCH);
        gemm_mma<<<grid, 256, SMEM_TOTAL>>>(nullptr, nullptr, (const uint32_t*)att,
                                            attS, NPIX,
                                            vH, vL, nullptr, nullptr, qtS, NPIX,
                                            NPIX, 3,
                                            outT, qtS, EMB,
                                            nullptr, nullptr, nullptr, nullptr, 0, 0,
                                            nullptr, nullptr);
    }
    // 7) residual + transpose
    {
        dim3 grid(EMB / 32, NPIX / 32, BATCH);
        epilogue_kernel<<<grid, dim3(32, 8)>>>(outT, vH, vL, out);
    }
}

// round 7
// speedup vs baseline: 1.3428x; 1.3428x over previous
#include <cuda_runtime.h>
#include <cuda_bf16.h>
#include <math.h>
#include <stdint.h>

// ---------------------------------------------------------------------------
// Problem constants
// ---------------------------------------------------------------------------
#define BATCH 8
#define CIN   256
#define EMB   512
#define HW    48
#define NPIX  2304
#define KDIM  2304

// ---------------------------------------------------------------------------
// Scratch: split hi/lo bf16 planes. ~297 MB total.
//  col planes aliased by fp32 att (softmax packs u32 in place).
//  qHi+qLo region aliased by fp32 outT (q dead after logits).
// ---------------------------------------------------------------------------
#define CBYT ((size_t)BATCH * NPIX * KDIM * 2)   // one col plane
#define WBYT ((size_t)EMB * KDIM * 2)
#define QBYT ((size_t)BATCH * NPIX * EMB * 2)

#define OFF_COLH ((size_t)0)
#define OFF_COLL (CBYT)
#define OFF_WQH  (2 * CBYT)
#define OFF_WQL  (OFF_WQH + WBYT)
#define OFF_WKH  (OFF_WQL + WBYT)
#define OFF_WKL  (OFF_WKH + WBYT)
#define OFF_WVH  (OFF_WKL + WBYT)
#define OFF_WVL  (OFF_WVH + WBYT)
#define OFF_QH   (OFF_WVL + WBYT)
#define OFF_QL   (OFF_QH + QBYT)
#define OFF_KH   (OFF_QL + QBYT)
#define OFF_KL   (OFF_KH + QBYT)
#define OFF_VH   (OFF_KL + QBYT)
#define OFF_VL   (OFF_VH + QBYT)
#define SCRATCH_BYTES (OFF_VL + QBYT)

__device__ __align__(1024) unsigned char g_scratch[SCRATCH_BYTES];

// ---------------------------------------------------------------------------
// Helpers
// ---------------------------------------------------------------------------
__device__ __forceinline__ uint32_t smem_u32(const void* p) {
    uint32_t a;
    asm("{ .reg .u64 t; cvta.to.shared.u64 t, %1; cvt.u32.u64 %0, t; }"
        : "=r"(a) : "l"(p));
    return a;
}

// SW64 swizzle: 16B column bits [4:6) ^= offset bits [7:9)
#define SWZ64(o) ((o) ^ (((o) >> 3) & 0x30))

__device__ __forceinline__ uint32_t pack_split(float x) {
    __nv_bfloat16 h = __float2bfloat16(x);
    float hf = __bfloat162float(h);
    __nv_bfloat16 l = __float2bfloat16(x - hf);
    return ((uint32_t)__bfloat16_as_ushort(h) << 16) | (uint32_t)__bfloat16_as_ushort(l);
}
__device__ __forceinline__ void split2(float x0, float x1, uint32_t& hi, uint32_t& lo) {
    __nv_bfloat16 h0 = __float2bfloat16(x0), h1 = __float2bfloat16(x1);
    __nv_bfloat16 l0 = __float2bfloat16(x0 - __bfloat162float(h0));
    __nv_bfloat16 l1 = __float2bfloat16(x1 - __bfloat162float(h1));
    hi = (uint32_t)__bfloat16_as_ushort(h0) | ((uint32_t)__bfloat16_as_ushort(h1) << 16);
    lo = (uint32_t)__bfloat16_as_ushort(l0) | ((uint32_t)__bfloat16_as_ushort(l1) << 16);
}

__device__ __forceinline__ void ldsm4(uint32_t& r0, uint32_t& r1, uint32_t& r2,
                                      uint32_t& r3, uint32_t addr) {
    asm volatile("ldmatrix.sync.aligned.m8n8.x4.shared.b16 {%0,%1,%2,%3}, [%4];"
                 : "=r"(r0), "=r"(r1), "=r"(r2), "=r"(r3) : "r"(addr));
}
__device__ __forceinline__ void mma16816(float* d, const uint32_t* a,
                                         const uint32_t* b) {
    asm volatile(
        "mma.sync.aligned.m16n8k16.row.col.f32.bf16.bf16.f32 "
        "{%0,%1,%2,%3},{%4,%5,%6,%7},{%8,%9},{%0,%1,%2,%3};"
        : "+f"(d[0]), "+f"(d[1]), "+f"(d[2]), "+f"(d[3])
        : "r"(a[0]), "r"(a[1]), "r"(a[2]), "r"(a[3]), "r"(b[0]), "r"(b[1]));
}
__device__ __forceinline__ void cp16(uint32_t s, const void* g) {
    asm volatile("cp.async.cg.shared.global [%0], [%1], 16;"
                 :: "r"(s), "l"(g) : "memory");
}
#define CP_COMMIT asm volatile("cp.async.commit_group;" ::: "memory")
#define CP_WAIT1  asm volatile("cp.async.wait_group 1;" ::: "memory")

__device__ __forceinline__ void sts64b(uint32_t addr, uint32_t lo, uint32_t hi) {
    unsigned long long v = ((unsigned long long)hi << 32) | lo;
    asm volatile("st.shared.b64 [%0], %1;" :: "r"(addr), "l"(v) : "memory");
}

// ---------------------------------------------------------------------------
// Converters
// ---------------------------------------------------------------------------
__global__ void pack_weights(const float* __restrict__ Wq, const float* __restrict__ Wk,
                             const float* __restrict__ Wv,
                             __nv_bfloat16* __restrict__ qh, __nv_bfloat16* __restrict__ ql,
                             __nv_bfloat16* __restrict__ kh, __nv_bfloat16* __restrict__ kl,
                             __nv_bfloat16* __restrict__ vh, __nv_bfloat16* __restrict__ vl)
{
    long i = (long)blockIdx.x * 256 + threadIdx.x;
    const long n = (long)EMB * KDIM;
    if (i >= n) return;
    float a = Wq[i], b = Wk[i], c = Wv[i];
    __nv_bfloat16 h;
    h = __float2bfloat16(a); qh[i] = h; ql[i] = __float2bfloat16(a - __bfloat162float(h));
    h = __float2bfloat16(b); kh[i] = h; kl[i] = __float2bfloat16(b - __bfloat162float(h));
    h = __float2bfloat16(c); vh[i] = h; vl[i] = __float2bfloat16(c - __bfloat162float(h));
}

__global__ void build_col(const float* __restrict__ feat,
                          __nv_bfloat16* __restrict__ cH, __nv_bfloat16* __restrict__ cL)
{
    long idx = (long)blockIdx.x * 256 + threadIdx.x;
    const long total = (long)BATCH * NPIX * KDIM;
    if (idx >= total) return;
    int k = (int)(idx % KDIM);
    long t = idx / KDIM;
    int n = (int)(t % NPIX);
    int b = (int)(t / NPIX);
    int c = k / 9, k9 = k - 9 * c;
    int ky = k9 / 3, kx = k9 - 3 * ky;
    int h = n / HW, w = n - HW * h;
    int hs = h + ky - 1, ws = w + kx - 1;
    float v = 0.f;
    if (hs >= 0 && hs < HW && ws >= 0 && ws < HW)
        v = feat[(((long)b * CIN + c) * HW + hs) * HW + ws];
    __nv_bfloat16 hh = __float2bfloat16(v);
    cH[idx] = hh;
    cL[idx] = __float2bfloat16(v - __bfloat162float(hh));
}

// ---------------------------------------------------------------------------
// Templated GEMM: D[m][n] = sum_k A[m][k]*B[n][k], split-bf16 3-MMA, fp32 acc.
// 256 threads, 8 warps as (BM/WM) x (BN/WN). KC=32, 3-stage cp.async pipeline.
// AMODE: 0 = A from split planes via cp.async; 1 = A packed u32 via LDG+PRMT.
// EPI:   0 = fp32 out | 1 = bias[n] + split planes (dual out, z&1) |
//        2 = bias[m] + split planes
// Stage layout: [Ah BM*64][Al BM*64][Bh BN*64][Bl BN*64]
// ---------------------------------------------------------------------------
template<int BM, int BN, int WM, int WN, int AMODE, int EPI>
__global__ __launch_bounds__(256, 1)
void gemm_tpl(const __nv_bfloat16* __restrict__ aHi, const __nv_bfloat16* __restrict__ aLo,
              const uint32_t* __restrict__ aPk, long sA, int lda,
              const __nv_bfloat16* __restrict__ bHi0, const __nv_bfloat16* __restrict__ bLo0,
              const __nv_bfloat16* __restrict__ bHi1, const __nv_bfloat16* __restrict__ bLo1,
              long sB, int ldb, int K,
              float* __restrict__ Cf, long sCf, int ldc,
              __nv_bfloat16* __restrict__ pH0, __nv_bfloat16* __restrict__ pL0,
              __nv_bfloat16* __restrict__ pH1, __nv_bfloat16* __restrict__ pL1,
              long sCp, int ldcp,
              const float* __restrict__ bias0, const float* __restrict__ bias1)
{
    constexpr int NWN    = BN / WN;           // warps along n
    constexpr int APLANE = BM * 64;
    constexpr int BPLANE = BN * 64;
    constexpr int STG    = 2 * APLANE + 2 * BPLANE;
    constexpr int CA     = BM / 32;           // per-thread A segments
    constexpr int CB     = BN / 32;
    constexpr int MI     = WM / 16;

    extern __shared__ __align__(128) unsigned char smem[];
    const uint32_t sbase = smem_u32(smem);
    const int tid = threadIdx.x, lid = tid & 31, wid = tid >> 5;
    const int warp_m = wid / NWN, warp_n = wid % NWN;

    int bz = blockIdx.z, b, wsel = 0;
    if (EPI == 1) { b = bz >> 1; wsel = bz & 1; } else { b = bz; }
    const int bm = blockIdx.y * BM, bn = blockIdx.x * BN;

    // ---- B loader mapping ----
    const __nv_bfloat16* BH = (EPI == 1 && wsel) ? bHi1 : bHi0;
    const __nv_bfloat16* BL = (EPI == 1 && wsel) ? bLo1 : bLo0;
    const __nv_bfloat16* bg[CB]; uint32_t bs_[CB];
#pragma unroll
    for (int i = 0; i < CB; i++) {
        int o = tid + 256 * i; int pl = o / (4 * BN); int rem = o - pl * 4 * BN;
        int r = rem >> 2; int c = rem & 3;
        bg[i] = (pl ? BL : BH) + (long)b * sB + (long)(bn + r) * ldb + c * 8;
        bs_[i] = 2u * APLANE + (uint32_t)pl * BPLANE + SWZ64((uint32_t)(r * 64 + c * 16));
    }
    // ---- A loader mapping ----
    const __nv_bfloat16* ag[CA]; uint32_t as_[CA];
    const uint32_t* apg[CA]; uint32_t ash[CA];
    if (AMODE == 0) {
#pragma unroll
        for (int i = 0; i < CA; i++) {
            int o = tid + 256 * i; int pl = o / (4 * BM); int rem = o - pl * 4 * BM;
            int r = rem >> 2; int c = rem & 3;
            ag[i] = (pl ? aLo : aHi) + (long)b * sA + (long)(bm + r) * lda + c * 8;
            as_[i] = (uint32_t)pl * APLANE + SWZ64((uint32_t)(r * 64 + c * 16));
        }
    } else {
#pragma unroll
        for (int i = 0; i < CA; i++) {
            int o = tid + 256 * i; int r = o >> 3; int seg = o & 7;
            apg[i] = aPk + (long)b * sA + (long)(bm + r) * lda + seg * 4;
            ash[i] = SWZ64((uint32_t)(r * 64 + seg * 8));
        }
    }

    uint4 rga[CA];
    auto issue_a = [&](int c, int st) {
        uint32_t ab = sbase + (uint32_t)st * STG;
#pragma unroll
        for (int i = 0; i < CA; i++) cp16(ab + as_[i], ag[i] + (long)c * 32);
    };
    auto issue_b = [&](int c, int st) {
        uint32_t bb = sbase + (uint32_t)st * STG;
#pragma unroll
        for (int i = 0; i < CB; i++) cp16(bb + bs_[i], bg[i] + (long)c * 32);
    };
    auto ldg_a = [&](int c) {
#pragma unroll
        for (int i = 0; i < CA; i++) rga[i] = *(const uint4*)(apg[i] + (long)c * 32);
    };
    auto sts_a = [&](int st) {
        uint32_t ab = sbase + (uint32_t)st * STG;
#pragma unroll
        for (int i = 0; i < CA; i++) {
            sts64b(ab + ash[i],
                   __byte_perm(rga[i].x, rga[i].y, 0x7632),
                   __byte_perm(rga[i].z, rga[i].w, 0x7632));
            sts64b(ab + APLANE + ash[i],
                   __byte_perm(rga[i].x, rga[i].y, 0x5410),
                   __byte_perm(rga[i].z, rga[i].w, 0x5410));
        }
    };

    float acc[MI][4][4];
#pragma unroll
    for (int i = 0; i < MI; i++)
#pragma unroll
        for (int j = 0; j < 4; j++)
#pragma unroll
            for (int r = 0; r < 4; r++) acc[i][j][r] = 0.f;

    const int nchunk = K / 32;

    // prologue: chunks 0,1
    if (AMODE == 0) issue_a(0, 0); else { ldg_a(0); sts_a(0); }
    issue_b(0, 0);
    CP_COMMIT;
    if (AMODE == 0) issue_a(1, 1); else ldg_a(1);   // AMODE1: hold chunk1 in regs
    issue_b(1, 1);
    CP_COMMIT;

    const int sub = lid >> 3, l7 = lid & 7;
    const int arow0 = warp_m * WM + (sub & 1) * 8 + l7;
    const int brow  = warp_n * WN + (sub >> 1) * 8 + l7;

    for (int c = 0; c < nchunk; c++) {
        CP_WAIT1;
        __syncthreads();

        const int cn = c + 2, st2 = cn % 3;
        if (AMODE == 1) {
            if (c + 1 < nchunk) sts_a((c + 1) % 3);
            if (cn < nchunk) ldg_a(cn);
        } else if (cn < nchunk) {
            issue_a(cn, st2);
        }
        if (cn < nchunk) issue_b(cn, st2);
        CP_COMMIT;

        const uint32_t stA  = sbase + (uint32_t)(c % 3) * STG;
        const uint32_t stBh = stA + 2u * APLANE, stBl = stBh + BPLANE;

#pragma unroll
        for (int ks = 0; ks < 2; ks++) {
            // B fragments first (16 regs live)
            uint32_t bh[4][2], bl[4][2];
            const int bkb = ks * 16 + (sub & 1) * 8;
#pragma unroll
            for (int g2 = 0; g2 < 2; g2++) {
                const uint32_t off = SWZ64((uint32_t)((brow + g2 * 16) * 64 + bkb * 2));
                ldsm4(bh[2 * g2][0], bh[2 * g2][1], bh[2 * g2 + 1][0],
                      bh[2 * g2 + 1][1], stBh + off);
                ldsm4(bl[2 * g2][0], bl[2 * g2][1], bl[2 * g2 + 1][0],
                      bl[2 * g2 + 1][1], stBl + off);
            }
            const int akb = ks * 16 + (sub >> 1) * 8;
#pragma unroll
            for (int i = 0; i < MI; i++) {
                uint32_t ah[4], al[4];
                const uint32_t off = SWZ64((uint32_t)((arow0 + i * 16) * 64 + akb * 2));
                ldsm4(ah[0], ah[1], ah[2], ah[3], stA + off);
                ldsm4(al[0], al[1], al[2], al[3], stA + APLANE + off);
#pragma unroll
                for (int j = 0; j < 4; j++) {
                    mma16816(acc[i][j], ah, bh[j]);
                    mma16816(acc[i][j], ah, bl[j]);
                    mma16816(acc[i][j], al, bh[j]);
                }
            }
        }
    }

    // ---- epilogue ----
    const float* bias = (EPI == 1) ? (wsel ? bias1 : bias0) : bias0;
#pragma unroll
    for (int i = 0; i < MI; i++)
#pragma unroll
        for (int j = 0; j < 4; j++) {
            const int m = bm + warp_m * WM + i * 16 + (lid >> 2);
            const int n = bn + warp_n * WN + j * 8 + (lid & 3) * 2;
            const float d0 = acc[i][j][0], d1 = acc[i][j][1];
            const float d2 = acc[i][j][2], d3 = acc[i][j][3];
            if (EPI == 0) {
                float* bp = Cf + (long)b * sCf;
                *(float2*)(bp + (long)m * ldc + n)       = make_float2(d0, d1);
                *(float2*)(bp + (long)(m + 8) * ldc + n) = make_float2(d2, d3);
            } else if (EPI == 1) {
                __nv_bfloat16* dH = (wsel ? pH1 : pH0) + (long)b * sCp;
                __nv_bfloat16* dL = (wsel ? pL1 : pL0) + (long)b * sCp;
                const float b0 = bias[n], b1 = bias[n + 1];
                uint32_t h, l;
                split2(d0 + b0, d1 + b1, h, l);
                *(uint32_t*)(dH + (long)m * ldcp + n) = h;
                *(uint32_t*)(dL + (long)m * ldcp + n) = l;
                split2(d2 + b0, d3 + b1, h, l);
                *(uint32_t*)(dH + (long)(m + 8) * ldcp + n) = h;
                *(uint32_t*)(dL + (long)(m + 8) * ldcp + n) = l;
            } else {
                __nv_bfloat16* dH = pH0 + (long)b * sCp;
                __nv_bfloat16* dL = pL0 + (long)b * sCp;
                const float bm0 = bias[m], bm8 = bias[m + 8];
                uint32_t h, l;
                split2(d0 + bm0, d1 + bm0, h, l);
                *(uint32_t*)(dH + (long)m * ldcp + n) = h;
                *(uint32_t*)(dL + (long)m * ldcp + n) = l;
                split2(d2 + bm8, d3 + bm8, h, l);
                *(uint32_t*)(dH + (long)(m + 8) * ldcp + n) = h;
                *(uint32_t*)(dL + (long)(m + 8) * ldcp + n) = l;
            }
        }
}

// ---------------------------------------------------------------------------
// Softmax over rows of att (fp32 in), writes packed split u32 IN PLACE.
// ---------------------------------------------------------------------------
__global__ __launch_bounds__(256)
void softmax_pack(float* __restrict__ att)
{
    const long row = blockIdx.x;
    float* p = att + row * NPIX;
    uint32_t* pu = (uint32_t*)p;
    __shared__ float red[256];
    const int t = threadIdx.x;

    float vals[9];
    float m = -INFINITY;
#pragma unroll
    for (int i = 0; i < 9; i++) {
        vals[i] = p[t + i * 256];
        m = fmaxf(m, vals[i]);
    }
    red[t] = m; __syncthreads();
    for (int s = 128; s > 0; s >>= 1) {
        if (t < s) red[t] = fmaxf(red[t], red[t + s]);
        __syncthreads();
    }
    m = red[0]; __syncthreads();

    float sum = 0.f;
#pragma unroll
    for (int i = 0; i < 9; i++) {
        vals[i] = __expf(vals[i] - m);
        sum += vals[i];
    }
    red[t] = sum; __syncthreads();
    for (int s = 128; s > 0; s >>= 1) {
        if (t < s) red[t] += red[t + s];
        __syncthreads();
    }
    const float inv = 1.f / red[0];
#pragma unroll
    for (int i = 0; i < 9; i++)
        pu[t + i * 256] = pack_split(vals[i] * inv);
}

// ---------------------------------------------------------------------------
// Final: out[b][e][n] = outT[b][n][e] + (vHi[b][e][n] + vLo[b][e][n])
// ---------------------------------------------------------------------------
__global__ void epilogue_kernel(const float* __restrict__ outT,
                                const __nv_bfloat16* __restrict__ vH,
                                const __nv_bfloat16* __restrict__ vL,
                                float* __restrict__ out)
{
    __shared__ float tile[32][33];
    const int b = blockIdx.z;
    const float* src = outT + (long)b * NPIX * EMB;   // [N][E]
    const __nv_bfloat16* vh = vH + (long)b * EMB * NPIX;
    const __nv_bfloat16* vl = vL + (long)b * EMB * NPIX;
    float* ob = out + (long)b * EMB * NPIX;
    const int e0 = blockIdx.x * 32;
    const int n0 = blockIdx.y * 32;
    const int tx = threadIdx.x, ty = threadIdx.y;     // 32 x 8
#pragma unroll
    for (int i = 0; i < 32; i += 8)
        tile[ty + i][tx] = src[(long)(n0 + ty + i) * EMB + (e0 + tx)];
    __syncthreads();
#pragma unroll
    for (int i = 0; i < 32; i += 8) {
        long o = (long)(e0 + ty + i) * NPIX + (n0 + tx);
        ob[o] = tile[tx][ty + i] + __bfloat162float(vh[o]) + __bfloat162float(vl[o]);
    }
}

// ---------------------------------------------------------------------------
// launch
// ---------------------------------------------------------------------------
extern "C" void kernel_launch(void* const* d_in, const int* in_sizes, int n_in,
                              void* d_out, int out_size)
{
    const float* feat = (const float*)d_in[0];
    const float* Wq   = (const float*)d_in[1];
    const float* bq   = (const float*)d_in[2];
    const float* Wk   = (const float*)d_in[3];
    const float* bk   = (const float*)d_in[4];
    const float* Wv   = (const float*)d_in[5];
    const float* bv   = (const float*)d_in[6];
    float* out = (float*)d_out;

    unsigned char* base;
    cudaGetSymbolAddress((void**)&base, g_scratch);
    __nv_bfloat16* colH = (__nv_bfloat16*)(base + OFF_COLH);
    __nv_bfloat16* colL = (__nv_bfloat16*)(base + OFF_COLL);
    __nv_bfloat16* wqH  = (__nv_bfloat16*)(base + OFF_WQH);
    __nv_bfloat16* wqL  = (__nv_bfloat16*)(base + OFF_WQL);
    __nv_bfloat16* wkH  = (__nv_bfloat16*)(base + OFF_WKH);
    __nv_bfloat16* wkL  = (__nv_bfloat16*)(base + OFF_WKL);
    __nv_bfloat16* wvH  = (__nv_bfloat16*)(base + OFF_WVH);
    __nv_bfloat16* wvL  = (__nv_bfloat16*)(base + OFF_WVL);
    __nv_bfloat16* qH   = (__nv_bfloat16*)(base + OFF_QH);
    __nv_bfloat16* qL   = (__nv_bfloat16*)(base + OFF_QL);
    __nv_bfloat16* kH   = (__nv_bfloat16*)(base + OFF_KH);
    __nv_bfloat16* kL   = (__nv_bfloat16*)(base + OFF_KL);
    __nv_bfloat16* vH   = (__nv_bfloat16*)(base + OFF_VH);
    __nv_bfloat16* vL   = (__nv_bfloat16*)(base + OFF_VL);
    float* att  = (float*)(base + OFF_COLH);   // alias; col planes dead by then
    float* outT = (float*)(base + OFF_QH);     // alias; q planes dead by then

    // smem sizes per instantiation
    const int SM_BIG = 3 * (2 * 192 * 64 + 2 * 128 * 64);   // 122880
    const int SM_SML = 3 * (2 * 128 * 64 + 2 * 128 * 64);   //  98304

    auto kQK  = gemm_tpl<192, 128, 96, 32, 0, 1>;
    auto kV   = gemm_tpl<128, 128, 64, 32, 0, 2>;
    auto kLOG = gemm_tpl<192, 128, 96, 32, 0, 0>;
    auto kOUT = gemm_tpl<128, 128, 64, 32, 1, 0>;
    cudaFuncSetAttribute(kQK,  cudaFuncAttributeMaxDynamicSharedMemorySize, SM_BIG);
    cudaFuncSetAttribute(kV,   cudaFuncAttributeMaxDynamicSharedMemorySize, SM_SML);
    cudaFuncSetAttribute(kLOG, cudaFuncAttributeMaxDynamicSharedMemorySize, SM_BIG);
    cudaFuncSetAttribute(kOUT, cudaFuncAttributeMaxDynamicSharedMemorySize, SM_SML);

    // 1) converters
    {
        long n = (long)EMB * KDIM;
        pack_weights<<<(unsigned)((n + 255) / 256), 256>>>(Wq, Wk, Wv,
                                                           wqH, wqL, wkH, wkL, wvH, wvL);
        long total = (long)BATCH * NPIX * KDIM;
        build_col<<<(unsigned)((total + 255) / 256), 256>>>(feat, colH, colL);
    }

    const long colS = (long)NPIX * KDIM;
    const long qtS  = (long)NPIX * EMB;
    const long attS = (long)NPIX * NPIX;

    // 2) q,k conv: D[n][e] = col[n][:] . W[e][:] + bias[e]
    {
        dim3 grid(EMB / 128, NPIX / 192, 2 * BATCH);
        kQK<<<grid, 256, SM_BIG>>>(colH, colL, nullptr, colS, KDIM,
                                   wqH, wqL, wkH, wkL, 0, KDIM, KDIM,
                                   nullptr, 0, 0,
                                   qH, qL, kH, kL, qtS, EMB,
                                   bq, bk);
    }
    // 3) v conv: D[e][n] = Wv[e][:] . col[n][:] + bias[e]
    {
        dim3 grid(NPIX / 128, EMB / 128, BATCH);
        kV<<<grid, 256, SM_SML>>>(wvH, wvL, nullptr, 0, KDIM,
                                  colH, colL, nullptr, nullptr, colS, KDIM, KDIM,
                                  nullptr, 0, 0,
                                  vH, vL, nullptr, nullptr, qtS, NPIX,
                                  bv, nullptr);
    }
    // 4) logits: att[i][j] = q[i][:] . k[j][:]   (K=512)
    {
        dim3 grid(NPIX / 128, NPIX / 192, BATCH);
        kLOG<<<grid, 256, SM_BIG>>>(qH, qL, nullptr, qtS, EMB,
                                    kH, kL, nullptr, nullptr, qtS, EMB, EMB,
                                    att, attS, NPIX,
                                    nullptr, nullptr, nullptr, nullptr, 0, 0,
                                    nullptr, nullptr);
    }
    // 5) softmax rows + pack u32 in place
    softmax_pack<<<BATCH * NPIX, 256>>>(att);

    // 6) output: outT[i][e] = att[i][:] . v[e][:]  (K=2304; A packed)
    {
        dim3 grid(EMB / 128, NPIX / 128, BATCH);
        kOUT<<<grid, 256, SM_SML>>>(nullptr, nullptr, (const uint32_t*)att, attS, NPIX,
                                    vH, vL, nullptr, nullptr, qtS, NPIX, NPIX,
                                    outT, qtS, EMB,
                                    nullptr, nullptr, nullptr, nullptr, 0, 0,
                                    nullptr, nullptr);
    }
    // 7) residual + transpose
    {
        dim3 grid(EMB / 32, NPIX / 32, BATCH);
        epilogue_kernel<<<grid, dim3(32, 8)>>>(outT, vH, vL, out);
    }
}

// round 8
// speedup vs baseline: 1.4647x; 1.0908x over previous
#include <cuda_runtime.h>
#include <cuda_bf16.h>
#include <math.h>
#include <stdint.h>

// ---------------------------------------------------------------------------
// Problem constants
// ---------------------------------------------------------------------------
#define BATCH 8
#define CIN   256
#define EMB   512
#define HW    48
#define NPIX  2304
#define KDIM  2304

// ---------------------------------------------------------------------------
// Scratch (packed split u32: (bf16hi<<16)|bf16lo). ~297 MB.
//   COL aliased -> fp32 att -> packed att (softmax in place)
//   QT  aliased -> fp32 outT (q dead after logits)
// ---------------------------------------------------------------------------
#define COL_BYTES ((size_t)BATCH * NPIX * KDIM * 4)
#define W_BYTES   ((size_t)EMB * KDIM * 4)
#define QT_BYTES  ((size_t)BATCH * NPIX * EMB * 4)

#define OFF_COL  ((size_t)0)
#define OFF_WQ   (OFF_COL + COL_BYTES)
#define OFF_WK   (OFF_WQ + W_BYTES)
#define OFF_WV   (OFF_WK + W_BYTES)
#define OFF_QT   (OFF_WV + W_BYTES)
#define OFF_KT   (OFF_QT + QT_BYTES)
#define OFF_VP   (OFF_KT + QT_BYTES)
#define SCRATCH_BYTES (OFF_VP + QT_BYTES)

__device__ __align__(1024) unsigned char g_scratch[SCRATCH_BYTES];

// ---------------------------------------------------------------------------
// Helpers
// ---------------------------------------------------------------------------
__device__ __forceinline__ uint32_t smem_u32(const void* p) {
    uint32_t a;
    asm("{ .reg .u64 t; cvta.to.shared.u64 t, %1; cvt.u32.u64 %0, t; }"
        : "=r"(a) : "l"(p));
    return a;
}

// SW64 swizzle: 16B column bits [4:6) ^= offset bits [7:9)
#define SWZ64(o) ((o) ^ (((o) >> 3) & 0x30))

__device__ __forceinline__ uint32_t pack_split(float x) {
    __nv_bfloat16 h = __float2bfloat16(x);
    float hf = __bfloat162float(h);
    __nv_bfloat16 l = __float2bfloat16(x - hf);
    return ((uint32_t)__bfloat16_as_ushort(h) << 16) | (uint32_t)__bfloat16_as_ushort(l);
}
__device__ __forceinline__ float unpack_split(uint32_t p) {
    float hi = __bfloat162float(__ushort_as_bfloat16((unsigned short)(p >> 16)));
    float lo = __bfloat162float(__ushort_as_bfloat16((unsigned short)(p & 0xFFFF)));
    return hi + lo;
}

__device__ __forceinline__ void ldsm4(uint32_t& r0, uint32_t& r1, uint32_t& r2,
                                      uint32_t& r3, uint32_t addr) {
    asm volatile("ldmatrix.sync.aligned.m8n8.x4.shared.b16 {%0,%1,%2,%3}, [%4];"
                 : "=r"(r0), "=r"(r1), "=r"(r2), "=r"(r3) : "r"(addr));
}
__device__ __forceinline__ void mma16816(float* d, const uint32_t* a,
                                         const uint32_t* b) {
    asm volatile(
        "mma.sync.aligned.m16n8k16.row.col.f32.bf16.bf16.f32 "
        "{%0,%1,%2,%3},{%4,%5,%6,%7},{%8,%9},{%0,%1,%2,%3};"
        : "+f"(d[0]), "+f"(d[1]), "+f"(d[2]), "+f"(d[3])
        : "r"(a[0]), "r"(a[1]), "r"(a[2]), "r"(a[3]), "r"(b[0]), "r"(b[1]));
}
__device__ __forceinline__ void sts64b(uint32_t addr, uint32_t lo, uint32_t hi) {
    unsigned long long v = ((unsigned long long)hi << 32) | lo;
    asm volatile("st.shared.b64 [%0], %1;" :: "r"(addr), "l"(v) : "memory");
}

// ---------------------------------------------------------------------------
// Converters (packed u32)
// ---------------------------------------------------------------------------
__global__ void pack_weights(const float* __restrict__ Wq, const float* __restrict__ Wk,
                             const float* __restrict__ Wv,
                             uint32_t* __restrict__ oq, uint32_t* __restrict__ ok,
                             uint32_t* __restrict__ ov)
{
    long i = (long)blockIdx.x * 256 + threadIdx.x;
    const long n = (long)EMB * KDIM;
    if (i >= n) return;
    oq[i] = pack_split(Wq[i]);
    ok[i] = pack_split(Wk[i]);
    ov[i] = pack_split(Wv[i]);
}

__global__ void build_colT(const float* __restrict__ feat, uint32_t* __restrict__ colT)
{
    long idx = (long)blockIdx.x * 256 + threadIdx.x;
    const long total = (long)BATCH * NPIX * KDIM;
    if (idx >= total) return;
    int k = (int)(idx % KDIM);
    long t = idx / KDIM;
    int n = (int)(t % NPIX);
    int b = (int)(t / NPIX);
    int c = k / 9, k9 = k - 9 * c;
    int ky = k9 / 3, kx = k9 - 3 * ky;
    int h = n / HW, w = n - HW * h;
    int hs = h + ky - 1, ws = w + kx - 1;
    float v = 0.f;
    if (hs >= 0 && hs < HW && ws >= 0 && ws < HW)
        v = feat[(((long)b * CIN + c) * HW + hs) * HW + ws];
    colT[idx] = pack_split(v);
}

// ---------------------------------------------------------------------------
// Templated GEMM: D[m][n] = sum_k A[m][k]*B[n][k], split-bf16 3-MMA, fp32 acc.
// All operands packed-split u32. LDG(uint4)->PRMT split->STS, double buffer,
// KC=32. 256 threads, 8 warps as 2 x 4; warp tile (BM/2) x 32.
// MODE: 0 fp32 out | 1 q/k conv (bias[col], packed out, z&1 selects) |
//       2 v conv (bias[row], packed out)
// Stage: [Ah BM*64][Al BM*64][Bh 8K][Bl 8K]
// ---------------------------------------------------------------------------
template<int BM, int MODE>
__global__ __launch_bounds__(256, 1)
void gemm_mma(const uint32_t* __restrict__ A, long sA, int lda,
              const uint32_t* __restrict__ B, long sB, int ldb,
              const uint32_t* __restrict__ Balt,
              int K,
              float* __restrict__ Cf, long sCf, int ldc,
              uint32_t* __restrict__ Cp, uint32_t* __restrict__ Cp2,
              long sCp, int ldcp,
              const float* __restrict__ bias0, const float* __restrict__ bias1)
{
    constexpr int APLANE = BM * 64;
    constexpr int BPLANE = 128 * 64;
    constexpr int STG    = 2 * APLANE + 2 * BPLANE;
    constexpr int CA     = BM / 32;   // uint4 per thread for A
    constexpr int MI     = BM / 32;   // 16-row m-blocks per warp (WM = BM/2)
    constexpr int WM     = BM / 2;

    extern __shared__ __align__(128) unsigned char smem[];
    const uint32_t sbase = smem_u32(smem);
    const int tid = threadIdx.x, lid = tid & 31, wid = tid >> 5;
    const int warp_m = wid >> 2, warp_n = wid & 3;

    int bz = blockIdx.z, b, wsel = 0;
    if (MODE == 1) { b = bz >> 1; wsel = bz & 1; } else { b = bz; }
    const int bm = blockIdx.y * BM, bn = blockIdx.x * 128;

    const uint32_t* Ab = A + (long)b * sA;
    const uint32_t* Bb = (MODE == 1) ? (wsel ? Balt : B) : (B + (long)b * sB);

    // ---- loader mappings: uint4 segments (8 per row of 32 u32) ----
    const uint32_t* apg[CA]; uint32_t ash[CA];
#pragma unroll
    for (int i = 0; i < CA; i++) {
        int f = tid + 256 * i; int r = f >> 3; int seg = f & 7;
        apg[i] = Ab + (long)(bm + r) * lda + seg * 4;
        ash[i] = SWZ64((uint32_t)(r * 64 + seg * 8));
    }
    const uint32_t* bpg[4]; uint32_t bsh[4];
#pragma unroll
    for (int i = 0; i < 4; i++) {
        int f = tid + 256 * i; int r = f >> 3; int seg = f & 7;
        bpg[i] = Bb + (long)(bn + r) * ldb + seg * 4;
        bsh[i] = SWZ64((uint32_t)(r * 64 + seg * 8));
    }

    uint4 rga[CA], rgb[4];
    auto ldg_all = [&](int c) {
#pragma unroll
        for (int i = 0; i < CA; i++) rga[i] = *(const uint4*)(apg[i] + (long)c * 32);
#pragma unroll
        for (int i = 0; i < 4; i++)  rgb[i] = *(const uint4*)(bpg[i] + (long)c * 32);
    };
    auto sts_all = [&](int st) {
        const uint32_t ab = sbase + (uint32_t)st * STG;
        const uint32_t bb = ab + 2u * APLANE;
#pragma unroll
        for (int i = 0; i < CA; i++) {
            sts64b(ab + ash[i],
                   __byte_perm(rga[i].x, rga[i].y, 0x7632),
                   __byte_perm(rga[i].z, rga[i].w, 0x7632));
            sts64b(ab + APLANE + ash[i],
                   __byte_perm(rga[i].x, rga[i].y, 0x5410),
                   __byte_perm(rga[i].z, rga[i].w, 0x5410));
        }
#pragma unroll
        for (int i = 0; i < 4; i++) {
            sts64b(bb + bsh[i],
                   __byte_perm(rgb[i].x, rgb[i].y, 0x7632),
                   __byte_perm(rgb[i].z, rgb[i].w, 0x7632));
            sts64b(bb + BPLANE + bsh[i],
                   __byte_perm(rgb[i].x, rgb[i].y, 0x5410),
                   __byte_perm(rgb[i].z, rgb[i].w, 0x5410));
        }
    };

    float acc[MI][4][4];
#pragma unroll
    for (int i = 0; i < MI; i++)
#pragma unroll
        for (int j = 0; j < 4; j++)
#pragma unroll
            for (int r = 0; r < 4; r++) acc[i][j][r] = 0.f;

    const int nchunk = K / 32;

    // prologue
    ldg_all(0);
    sts_all(0);
    __syncthreads();

    const int sub = lid >> 3, l7 = lid & 7;
    const int arow0 = warp_m * WM + (sub & 1) * 8 + l7;
    const int brow  = warp_n * 32 + (sub >> 1) * 8 + l7;

    for (int c = 0; c < nchunk; c++) {
        if (c + 1 < nchunk) ldg_all(c + 1);

        const uint32_t stA  = sbase + (uint32_t)(c & 1) * STG;
        const uint32_t stBh = stA + 2u * APLANE, stBl = stBh + BPLANE;

#pragma unroll
        for (int ks = 0; ks < 2; ks++) {
            // B fragments first (16 regs live)
            uint32_t bh[4][2], bl[4][2];
            const int bkb = ks * 16 + (sub & 1) * 8;
#pragma unroll
            for (int g2 = 0; g2 < 2; g2++) {
                const uint32_t off = SWZ64((uint32_t)((brow + g2 * 16) * 64 + bkb * 2));
                ldsm4(bh[2 * g2][0], bh[2 * g2][1], bh[2 * g2 + 1][0],
                      bh[2 * g2 + 1][1], stBh + off);
                ldsm4(bl[2 * g2][0], bl[2 * g2][1], bl[2 * g2 + 1][0],
                      bl[2 * g2 + 1][1], stBl + off);
            }
            const int akb = ks * 16 + (sub >> 1) * 8;
#pragma unroll
            for (int i = 0; i < MI; i++) {
                uint32_t ah[4], al[4];
                const uint32_t off = SWZ64((uint32_t)((arow0 + i * 16) * 64 + akb * 2));
                ldsm4(ah[0], ah[1], ah[2], ah[3], stA + off);
                ldsm4(al[0], al[1], al[2], al[3], stA + APLANE + off);
#pragma unroll
                for (int j = 0; j < 4; j++) {
                    mma16816(acc[i][j], ah, bh[j]);
                    mma16816(acc[i][j], ah, bl[j]);
                    mma16816(acc[i][j], al, bh[j]);
                }
            }
        }

        if (c + 1 < nchunk) sts_all((c + 1) & 1);
        __syncthreads();
    }

    // ---- epilogue ----
    const float* bias = (MODE == 1) ? (wsel ? bias1 : bias0) : bias0;
#pragma unroll
    for (int i = 0; i < MI; i++)
#pragma unroll
        for (int j = 0; j < 4; j++) {
            const int m = bm + warp_m * WM + i * 16 + (lid >> 2);
            const int n = bn + warp_n * 32 + j * 8 + (lid & 3) * 2;
            const float d0 = acc[i][j][0], d1 = acc[i][j][1];
            const float d2 = acc[i][j][2], d3 = acc[i][j][3];
            if (MODE == 0) {
                float* bp = Cf + (long)b * sCf;
                *(float2*)(bp + (long)m * ldc + n)       = make_float2(d0, d1);
                *(float2*)(bp + (long)(m + 8) * ldc + n) = make_float2(d2, d3);
            } else if (MODE == 1) {
                uint32_t* dst = (wsel ? Cp2 : Cp) + (long)b * sCp;
                const float b0 = bias[n], b1 = bias[n + 1];
                *(uint2*)(dst + (long)m * ldcp + n) =
                    make_uint2(pack_split(d0 + b0), pack_split(d1 + b1));
                *(uint2*)(dst + (long)(m + 8) * ldcp + n) =
                    make_uint2(pack_split(d2 + b0), pack_split(d3 + b1));
            } else {
                uint32_t* bp = Cp + (long)b * sCp;
                const float bm0 = bias[m], bm8 = bias[m + 8];
                *(uint2*)(bp + (long)m * ldcp + n) =
                    make_uint2(pack_split(d0 + bm0), pack_split(d1 + bm0));
                *(uint2*)(bp + (long)(m + 8) * ldcp + n) =
                    make_uint2(pack_split(d2 + bm8), pack_split(d3 + bm8));
            }
        }
}

// ---------------------------------------------------------------------------
// Softmax over rows of att (fp32 in), writes packed split u32 IN PLACE.
// ---------------------------------------------------------------------------
__global__ __launch_bounds__(256)
void softmax_pack(float* __restrict__ att)
{
    const long row = blockIdx.x;
    float* p = att + row * NPIX;
    uint32_t* pu = (uint32_t*)p;
    __shared__ float red[256];
    const int t = threadIdx.x;

    float vals[9];
    float m = -INFINITY;
#pragma unroll
    for (int i = 0; i < 9; i++) {
        vals[i] = p[t + i * 256];
        m = fmaxf(m, vals[i]);
    }
    red[t] = m; __syncthreads();
    for (int s = 128; s > 0; s >>= 1) {
        if (t < s) red[t] = fmaxf(red[t], red[t + s]);
        __syncthreads();
    }
    m = red[0]; __syncthreads();

    float sum = 0.f;
#pragma unroll
    for (int i = 0; i < 9; i++) {
        vals[i] = __expf(vals[i] - m);
        sum += vals[i];
    }
    red[t] = sum; __syncthreads();
    for (int s = 128; s > 0; s >>= 1) {
        if (t < s) red[t] += red[t + s];
        __syncthreads();
    }
    const float inv = 1.f / red[0];
#pragma unroll
    for (int i = 0; i < 9; i++)
        pu[t + i * 256] = pack_split(vals[i] * inv);
}

// ---------------------------------------------------------------------------
// Final: out[b][e][n] = outT[b][n][e] + unpack(vP[b][e][n])
// ---------------------------------------------------------------------------
__global__ void epilogue_kernel(const float* __restrict__ outT,
                                const uint32_t* __restrict__ vP,
                                float* __restrict__ out)
{
    __shared__ float tile[32][33];
    const int b = blockIdx.z;
    const float*    src = outT + (long)b * NPIX * EMB;   // [N][E]
    const uint32_t* vb  = vP   + (long)b * EMB  * NPIX;  // [E][N] packed
    float*          ob  = out  + (long)b * EMB  * NPIX;  // [E][N]
    const int e0 = blockIdx.x * 32;
    const int n0 = blockIdx.y * 32;
    const int tx = threadIdx.x, ty = threadIdx.y;        // 32 x 8
#pragma unroll
    for (int i = 0; i < 32; i += 8)
        tile[ty + i][tx] = src[(long)(n0 + ty + i) * EMB + (e0 + tx)];
    __syncthreads();
#pragma unroll
    for (int i = 0; i < 32; i += 8) {
        long o = (long)(e0 + ty + i) * NPIX + (n0 + tx);
        ob[o] = tile[tx][ty + i] + unpack_split(vb[o]);
    }
}

// ---------------------------------------------------------------------------
// launch
// ---------------------------------------------------------------------------
extern "C" void kernel_launch(void* const* d_in, const int* in_sizes, int n_in,
                              void* d_out, int out_size)
{
    const float* feat = (const float*)d_in[0];
    const float* Wq   = (const float*)d_in[1];
    const float* bq   = (const float*)d_in[2];
    const float* Wk   = (const float*)d_in[3];
    const float* bk   = (const float*)d_in[4];
    const float* Wv   = (const float*)d_in[5];
    const float* bv   = (const float*)d_in[6];
    float* out = (float*)d_out;

    unsigned char* base;
    cudaGetSymbolAddress((void**)&base, g_scratch);
    uint32_t* colT = (uint32_t*)(base + OFF_COL);
    uint32_t* wqP  = (uint32_t*)(base + OFF_WQ);
    uint32_t* wkP  = (uint32_t*)(base + OFF_WK);
    uint32_t* wvP  = (uint32_t*)(base + OFF_WV);
    uint32_t* qT   = (uint32_t*)(base + OFF_QT);
    uint32_t* kT   = (uint32_t*)(base + OFF_KT);
    uint32_t* vP   = (uint32_t*)(base + OFF_VP);
    float*    att  = (float*)   (base + OFF_COL);   // alias; colT dead by then
    float*    outT = (float*)   (base + OFF_QT);    // alias; qT dead by then

    const int SM_BIG = 2 * (2 * 192 * 64 + 2 * 128 * 64);   // 81920
    const int SM_SML = 2 * (2 * 128 * 64 + 2 * 128 * 64);   // 65536

    auto kQK  = gemm_mma<192, 1>;
    auto kV   = gemm_mma<128, 2>;
    auto kLOG = gemm_mma<192, 0>;
    auto kOUT = gemm_mma<128, 0>;
    cudaFuncSetAttribute(kQK,  cudaFuncAttributeMaxDynamicSharedMemorySize, SM_BIG);
    cudaFuncSetAttribute(kV,   cudaFuncAttributeMaxDynamicSharedMemorySize, SM_SML);
    cudaFuncSetAttribute(kLOG, cudaFuncAttributeMaxDynamicSharedMemorySize, SM_BIG);
    cudaFuncSetAttribute(kOUT, cudaFuncAttributeMaxDynamicSharedMemorySize, SM_SML);

    // 1) pack weights + build packed im2col
    {
        long n = (long)EMB * KDIM;
        pack_weights<<<(unsigned)((n + 255) / 256), 256>>>(Wq, Wk, Wv, wqP, wkP, wvP);
        long total = (long)BATCH * NPIX * KDIM;
        build_colT<<<(unsigned)((total + 255) / 256), 256>>>(feat, colT);
    }

    const long colS = (long)NPIX * KDIM;
    const long qtS  = (long)NPIX * EMB;
    const long attS = (long)NPIX * NPIX;

    // 2) q,k conv: D[n][e] = colT[n][:] . W[e][:] + bias[e]  (packed out)
    {
        dim3 grid(EMB / 128, NPIX / 192, 2 * BATCH);
        kQK<<<grid, 256, SM_BIG>>>(colT, colS, KDIM,
                                   wqP, 0, KDIM, wkP, KDIM,
                                   nullptr, 0, 0,
                                   qT, kT, qtS, EMB,
                                   bq, bk);
    }
    // 3) v conv: D[e][n] = Wv[e][:] . colT[n][:] + bias[e]  (packed out)
    {
        dim3 grid(NPIX / 128, EMB / 128, BATCH);
        kV<<<grid, 256, SM_SML>>>(wvP, 0, KDIM,
                                  colT, colS, KDIM, nullptr, KDIM,
                                  nullptr, 0, 0,
                                  vP, nullptr, qtS, NPIX,
                                  bv, nullptr);
    }
    // 4) logits: att[i][j] = qT[i][:] . kT[j][:]  (K=512, fp32 out)
    {
        dim3 grid(NPIX / 128, NPIX / 192, BATCH);
        kLOG<<<grid, 256, SM_BIG>>>(qT, qtS, EMB,
                                    kT, qtS, EMB, nullptr, EMB,
                                    att, attS, NPIX,
                                    nullptr, nullptr, 0, 0,
                                    nullptr, nullptr);
    }
    // 5) softmax rows + pack u32 in place
    softmax_pack<<<BATCH * NPIX, 256>>>(att);

    // 6) output: outT[i][e] = att[i][:] . vP[e][:]  (K=2304, fp32 out)
    {
        dim3 grid(EMB / 128, NPIX / 128, BATCH);
        kOUT<<<grid, 256, SM_SML>>>((const uint32_t*)att, attS, NPIX,
                                    vP, qtS, NPIX, nullptr, NPIX,
                                    outT, qtS, EMB,
                                    nullptr, nullptr, 0, 0,
                                    nullptr, nullptr);
    }
    // 7) residual + transpose
    {
        dim3 grid(EMB / 32, NPIX / 32, BATCH);
        epilogue_kernel<<<grid, dim3(32, 8)>>>(outT, vP, out);
    }
}

// round 9
// speedup vs baseline: 1.5840x; 1.0815x over previous
#include <cuda_runtime.h>
#include <cuda_bf16.h>
#include <math.h>
#include <stdint.h>

// ---------------------------------------------------------------------------
// Problem constants
// ---------------------------------------------------------------------------
#define BATCH 8
#define CIN   256
#define EMB   512
#define HW    48
#define NPIX  2304
#define KDIM  2304

// ---------------------------------------------------------------------------
// Scratch (packed split u32: (bf16hi<<16)|bf16lo). ~297 MB.
//   COL aliased -> fp32 att -> packed att (softmax in place)
//   QT  aliased -> fp32 outT (q dead after logits)
// ---------------------------------------------------------------------------
#define COL_BYTES ((size_t)BATCH * NPIX * KDIM * 4)
#define W_BYTES   ((size_t)EMB * KDIM * 4)
#define QT_BYTES  ((size_t)BATCH * NPIX * EMB * 4)

#define OFF_COL  ((size_t)0)
#define OFF_WQ   (OFF_COL + COL_BYTES)
#define OFF_WK   (OFF_WQ + W_BYTES)
#define OFF_WV   (OFF_WK + W_BYTES)
#define OFF_QT   (OFF_WV + W_BYTES)
#define OFF_KT   (OFF_QT + QT_BYTES)
#define OFF_VP   (OFF_KT + QT_BYTES)
#define SCRATCH_BYTES (OFF_VP + QT_BYTES)

__device__ __align__(1024) unsigned char g_scratch[SCRATCH_BYTES];

// ---------------------------------------------------------------------------
// Helpers
// ---------------------------------------------------------------------------
__device__ __forceinline__ uint32_t smem_u32(const void* p) {
    uint32_t a;
    asm("{ .reg .u64 t; cvta.to.shared.u64 t, %1; cvt.u32.u64 %0, t; }"
        : "=r"(a) : "l"(p));
    return a;
}

// SW64 swizzle: 16B column bits [4:6) ^= offset bits [7:9)
#define SWZ64(o) ((o) ^ (((o) >> 3) & 0x30))

__device__ __forceinline__ uint32_t pack_split(float x) {
    __nv_bfloat16 h = __float2bfloat16(x);
    float hf = __bfloat162float(h);
    __nv_bfloat16 l = __float2bfloat16(x - hf);
    return ((uint32_t)__bfloat16_as_ushort(h) << 16) | (uint32_t)__bfloat16_as_ushort(l);
}
__device__ __forceinline__ float unpack_split(uint32_t p) {
    float hi = __bfloat162float(__ushort_as_bfloat16((unsigned short)(p >> 16)));
    float lo = __bfloat162float(__ushort_as_bfloat16((unsigned short)(p & 0xFFFF)));
    return hi + lo;
}

__device__ __forceinline__ void ldsm4(uint32_t& r0, uint32_t& r1, uint32_t& r2,
                                      uint32_t& r3, uint32_t addr) {
    asm volatile("ldmatrix.sync.aligned.m8n8.x4.shared.b16 {%0,%1,%2,%3}, [%4];"
                 : "=r"(r0), "=r"(r1), "=r"(r2), "=r"(r3) : "r"(addr));
}
__device__ __forceinline__ void mma16816(float* d, const uint32_t* a,
                                         const uint32_t* b) {
    asm volatile(
        "mma.sync.aligned.m16n8k16.row.col.f32.bf16.bf16.f32 "
        "{%0,%1,%2,%3},{%4,%5,%6,%7},{%8,%9},{%0,%1,%2,%3};"
        : "+f"(d[0]), "+f"(d[1]), "+f"(d[2]), "+f"(d[3])
        : "r"(a[0]), "r"(a[1]), "r"(a[2]), "r"(a[3]), "r"(b[0]), "r"(b[1]));
}
__device__ __forceinline__ void sts64b(uint32_t addr, uint32_t lo, uint32_t hi) {
    unsigned long long v = ((unsigned long long)hi << 32) | lo;
    asm volatile("st.shared.b64 [%0], %1;" :: "r"(addr), "l"(v) : "memory");
}

// ---------------------------------------------------------------------------
// Converters (packed u32)
// ---------------------------------------------------------------------------
__global__ void pack_weights(const float* __restrict__ Wq, const float* __restrict__ Wk,
                             const float* __restrict__ Wv,
                             uint32_t* __restrict__ oq, uint32_t* __restrict__ ok,
                             uint32_t* __restrict__ ov)
{
    long i = (long)blockIdx.x * 256 + threadIdx.x;
    const long n = (long)EMB * KDIM;
    if (i >= n) return;
    oq[i] = pack_split(Wq[i]);
    ok[i] = pack_split(Wk[i]);
    ov[i] = pack_split(Wv[i]);
}

__global__ void build_colT(const float* __restrict__ feat, uint32_t* __restrict__ colT)
{
    long idx = (long)blockIdx.x * 256 + threadIdx.x;
    const long total = (long)BATCH * NPIX * KDIM;
    if (idx >= total) return;
    int k = (int)(idx % KDIM);
    long t = idx / KDIM;
    int n = (int)(t % NPIX);
    int b = (int)(t / NPIX);
    int c = k / 9, k9 = k - 9 * c;
    int ky = k9 / 3, kx = k9 - 3 * ky;
    int h = n / HW, w = n - HW * h;
    int hs = h + ky - 1, ws = w + kx - 1;
    float v = 0.f;
    if (hs >= 0 && hs < HW && ws >= 0 && ws < HW)
        v = feat[(((long)b * CIN + c) * HW + hs) * HW + ws];
    colT[idx] = pack_split(v);
}

// ---------------------------------------------------------------------------
// GEMM: D[m][n] = sum_k A[m][k]*B[n][k], split-bf16 3-MMA, fp32 acc.
// All operands packed-split u32. LDG(uint4)->PRMT split->STS.
// 128x128 CTA, 8 warps (2x4), warp 64x32, KC=32.
// FOUR smem stages, ONE __syncthreads per PAIR of chunks:
//   pair p reads stages {2p%4, (2p+1)%4}, writes {(2p+2)%4, (2p+3)%4}.
// MODE: 0 fp32 out | 1 q/k conv (bias[col], packed out, z&1 selects) |
//       2 v conv (bias[row], packed out)
// Stage: [Ah 8K][Al 8K][Bh 8K][Bl 8K] = 32KB; total smem 128KB.
// ---------------------------------------------------------------------------
#define STG 32768
#define SMEM_TOTAL (4 * STG)

template<int MODE>
__global__ __launch_bounds__(256, 1)
void gemm_mma(const uint32_t* __restrict__ A, long sA, int lda,
              const uint32_t* __restrict__ B, long sB, int ldb,
              const uint32_t* __restrict__ Balt,
              int K,
              float* __restrict__ Cf, long sCf, int ldc,
              uint32_t* __restrict__ Cp, uint32_t* __restrict__ Cp2,
              long sCp, int ldcp,
              const float* __restrict__ bias0, const float* __restrict__ bias1)
{
    extern __shared__ __align__(128) unsigned char smem[];
    const uint32_t sbase = smem_u32(smem);
    const int tid = threadIdx.x, lid = tid & 31, wid = tid >> 5;
    const int warp_m = wid >> 2, warp_n = wid & 3;

    int bz = blockIdx.z, b, wsel = 0;
    if (MODE == 1) { b = bz >> 1; wsel = bz & 1; } else { b = bz; }
    const int bm = blockIdx.y * 128, bn = blockIdx.x * 128;

    const uint32_t* Ab = A + (long)b * sA;
    const uint32_t* Bb = (MODE == 1) ? (wsel ? Balt : B) : (B + (long)b * sB);

    // ---- loader mappings: uint4 segments (8 per 32-u32 row) ----
    const uint32_t* apg[4]; uint32_t ash[4];
    const uint32_t* bpg[4]; uint32_t bsh[4];
#pragma unroll
    for (int i = 0; i < 4; i++) {
        int f = tid + 256 * i; int r = f >> 3; int seg = f & 7;
        apg[i] = Ab + (long)(bm + r) * lda + seg * 4;
        bpg[i] = Bb + (long)(bn + r) * ldb + seg * 4;
        ash[i] = SWZ64((uint32_t)(r * 64 + seg * 8));
        bsh[i] = ash[i];
    }

    uint4 rga[4], rgb[4];
    auto ldg_all = [&](int c) {
#pragma unroll
        for (int i = 0; i < 4; i++) rga[i] = *(const uint4*)(apg[i] + (long)c * 32);
#pragma unroll
        for (int i = 0; i < 4; i++) rgb[i] = *(const uint4*)(bpg[i] + (long)c * 32);
    };
    auto sts_all = [&](int st) {
        const uint32_t ab = sbase + (uint32_t)st * STG;
        const uint32_t bb = ab + 16384u;
#pragma unroll
        for (int i = 0; i < 4; i++) {
            sts64b(ab + ash[i],
                   __byte_perm(rga[i].x, rga[i].y, 0x7632),
                   __byte_perm(rga[i].z, rga[i].w, 0x7632));
            sts64b(ab + 8192u + ash[i],
                   __byte_perm(rga[i].x, rga[i].y, 0x5410),
                   __byte_perm(rga[i].z, rga[i].w, 0x5410));
        }
#pragma unroll
        for (int i = 0; i < 4; i++) {
            sts64b(bb + bsh[i],
                   __byte_perm(rgb[i].x, rgb[i].y, 0x7632),
                   __byte_perm(rgb[i].z, rgb[i].w, 0x7632));
            sts64b(bb + 8192u + bsh[i],
                   __byte_perm(rgb[i].x, rgb[i].y, 0x5410),
                   __byte_perm(rgb[i].z, rgb[i].w, 0x5410));
        }
    };

    float acc[4][4][4];
#pragma unroll
    for (int i = 0; i < 4; i++)
#pragma unroll
        for (int j = 0; j < 4; j++)
#pragma unroll
            for (int r = 0; r < 4; r++) acc[i][j][r] = 0.f;

    const int sub = lid >> 3, l7 = lid & 7;
    const int arow0 = warp_m * 64 + (sub & 1) * 8 + l7;
    const int brow  = warp_n * 32 + (sub >> 1) * 8 + l7;

    auto compute = [&](int st) {
        const uint32_t stA  = sbase + (uint32_t)st * STG;
        const uint32_t stBh = stA + 16384u, stBl = stA + 24576u;
#pragma unroll
        for (int ks = 0; ks < 2; ks++) {
            uint32_t bh[4][2], bl[4][2];
            const int bkb = ks * 16 + (sub & 1) * 8;
#pragma unroll
            for (int g2 = 0; g2 < 2; g2++) {
                const uint32_t off = SWZ64((uint32_t)((brow + g2 * 16) * 64 + bkb * 2));
                ldsm4(bh[2 * g2][0], bh[2 * g2][1], bh[2 * g2 + 1][0],
                      bh[2 * g2 + 1][1], stBh + off);
                ldsm4(bl[2 * g2][0], bl[2 * g2][1], bl[2 * g2 + 1][0],
                      bl[2 * g2 + 1][1], stBl + off);
            }
            const int akb = ks * 16 + (sub >> 1) * 8;
#pragma unroll
            for (int i = 0; i < 4; i++) {
                uint32_t ah[4], al[4];
                const uint32_t off = SWZ64((uint32_t)((arow0 + i * 16) * 64 + akb * 2));
                ldsm4(ah[0], ah[1], ah[2], ah[3], stA + off);
                ldsm4(al[0], al[1], al[2], al[3], stA + 8192u + off);
#pragma unroll
                for (int j = 0; j < 4; j++) {
                    mma16816(acc[i][j], ah, bh[j]);
                    mma16816(acc[i][j], ah, bl[j]);
                    mma16816(acc[i][j], al, bh[j]);
                }
            }
        }
    };

    const int nchunk = K / 32;          // always even here (72, 16, 72)
    const int npair  = nchunk / 2;

    // prologue: stage chunks 0 and 1
    ldg_all(0); sts_all(0);
    ldg_all(1); sts_all(1);
    __syncthreads();

    for (int p = 0; p < npair; p++) {
        const int c0 = 2 * p;
        // iter A: compute c0, stage c0+2
        if (c0 + 2 < nchunk) ldg_all(c0 + 2);
        compute(c0 & 3);
        if (c0 + 2 < nchunk) sts_all((c0 + 2) & 3);
        // iter B: compute c0+1, stage c0+3
        if (c0 + 3 < nchunk) ldg_all(c0 + 3);
        compute((c0 + 1) & 3);
        if (c0 + 3 < nchunk) sts_all((c0 + 3) & 3);
        __syncthreads();
    }

    // ---- epilogue ----
    const float* bias = (MODE == 1) ? (wsel ? bias1 : bias0) : bias0;
#pragma unroll
    for (int i = 0; i < 4; i++)
#pragma unroll
        for (int j = 0; j < 4; j++) {
            const int m = bm + warp_m * 64 + i * 16 + (lid >> 2);
            const int n = bn + warp_n * 32 + j * 8 + (lid & 3) * 2;
            const float d0 = acc[i][j][0], d1 = acc[i][j][1];
            const float d2 = acc[i][j][2], d3 = acc[i][j][3];
            if (MODE == 0) {
                float* bp = Cf + (long)b * sCf;
                *(float2*)(bp + (long)m * ldc + n)       = make_float2(d0, d1);
                *(float2*)(bp + (long)(m + 8) * ldc + n) = make_float2(d2, d3);
            } else if (MODE == 1) {
                uint32_t* dst = (wsel ? Cp2 : Cp) + (long)b * sCp;
                const float b0 = bias[n], b1 = bias[n + 1];
                *(uint2*)(dst + (long)m * ldcp + n) =
                    make_uint2(pack_split(d0 + b0), pack_split(d1 + b1));
                *(uint2*)(dst + (long)(m + 8) * ldcp + n) =
                    make_uint2(pack_split(d2 + b0), pack_split(d3 + b1));
            } else {
                uint32_t* bp = Cp + (long)b * sCp;
                const float bm0 = bias[m], bm8 = bias[m + 8];
                *(uint2*)(bp + (long)m * ldcp + n) =
                    make_uint2(pack_split(d0 + bm0), pack_split(d1 + bm0));
                *(uint2*)(bp + (long)(m + 8) * ldcp + n) =
                    make_uint2(pack_split(d2 + bm8), pack_split(d3 + bm8));
            }
        }
}

// ---------------------------------------------------------------------------
// Softmax over rows of att (fp32 in), writes packed split u32 IN PLACE.
// ---------------------------------------------------------------------------
__global__ __launch_bounds__(256)
void softmax_pack(float* __restrict__ att)
{
    const long row = blockIdx.x;
    float* p = att + row * NPIX;
    uint32_t* pu = (uint32_t*)p;
    __shared__ float red[256];
    const int t = threadIdx.x;

    float vals[9];
    float m = -INFINITY;
#pragma unroll
    for (int i = 0; i < 9; i++) {
        vals[i] = p[t + i * 256];
        m = fmaxf(m, vals[i]);
    }
    red[t] = m; __syncthreads();
    for (int s = 128; s > 0; s >>= 1) {
        if (t < s) red[t] = fmaxf(red[t], red[t + s]);
        __syncthreads();
    }
    m = red[0]; __syncthreads();

    float sum = 0.f;
#pragma unroll
    for (int i = 0; i < 9; i++) {
        vals[i] = __expf(vals[i] - m);
        sum += vals[i];
    }
    red[t] = sum; __syncthreads();
    for (int s = 128; s > 0; s >>= 1) {
        if (t < s) red[t] += red[t + s];
        __syncthreads();
    }
    const float inv = 1.f / red[0];
#pragma unroll
    for (int i = 0; i < 9; i++)
        pu[t + i * 256] = pack_split(vals[i] * inv);
}

// ---------------------------------------------------------------------------
// Final: out[b][e][n] = outT[b][n][e] + unpack(vP[b][e][n])
// ---------------------------------------------------------------------------
__global__ void epilogue_kernel(const float* __restrict__ outT,
                                const uint32_t* __restrict__ vP,
                                float* __restrict__ out)
{
    __shared__ float tile[32][33];
    const int b = blockIdx.z;
    const float*    src = outT + (long)b * NPIX * EMB;   // [N][E]
    const uint32_t* vb  = vP   + (long)b * EMB  * NPIX;  // [E][N] packed
    float*          ob  = out  + (long)b * EMB  * NPIX;  // [E][N]
    const int e0 = blockIdx.x * 32;
    const int n0 = blockIdx.y * 32;
    const int tx = threadIdx.x, ty = threadIdx.y;        // 32 x 8
#pragma unroll
    for (int i = 0; i < 32; i += 8)
        tile[ty + i][tx] = src[(long)(n0 + ty + i) * EMB + (e0 + tx)];
    __syncthreads();
#pragma unroll
    for (int i = 0; i < 32; i += 8) {
        long o = (long)(e0 + ty + i) * NPIX + (n0 + tx);
        ob[o] = tile[tx][ty + i] + unpack_split(vb[o]);
    }
}

// ---------------------------------------------------------------------------
// launch
// ---------------------------------------------------------------------------
extern "C" void kernel_launch(void* const* d_in, const int* in_sizes, int n_in,
                              void* d_out, int out_size)
{
    const float* feat = (const float*)d_in[0];
    const float* Wq   = (const float*)d_in[1];
    const float* bq   = (const float*)d_in[2];
    const float* Wk   = (const float*)d_in[3];
    const float* bk   = (const float*)d_in[4];
    const float* Wv   = (const float*)d_in[5];
    const float* bv   = (const float*)d_in[6];
    float* out = (float*)d_out;

    unsigned char* base;
    cudaGetSymbolAddress((void**)&base, g_scratch);
    uint32_t* colT = (uint32_t*)(base + OFF_COL);
    uint32_t* wqP  = (uint32_t*)(base + OFF_WQ);
    uint32_t* wkP  = (uint32_t*)(base + OFF_WK);
    uint32_t* wvP  = (uint32_t*)(base + OFF_WV);
    uint32_t* qT   = (uint32_t*)(base + OFF_QT);
    uint32_t* kT   = (uint32_t*)(base + OFF_KT);
    uint32_t* vP   = (uint32_t*)(base + OFF_VP);
    float*    att  = (float*)   (base + OFF_COL);   // alias; colT dead by then
    float*    outT = (float*)   (base + OFF_QT);    // alias; qT dead by then

    auto kQK  = gemm_mma<1>;
    auto kV   = gemm_mma<2>;
    auto kGEN = gemm_mma<0>;
    cudaFuncSetAttribute(kQK,  cudaFuncAttributeMaxDynamicSharedMemorySize, SMEM_TOTAL);
    cudaFuncSetAttribute(kV,   cudaFuncAttributeMaxDynamicSharedMemorySize, SMEM_TOTAL);
    cudaFuncSetAttribute(kGEN, cudaFuncAttributeMaxDynamicSharedMemorySize, SMEM_TOTAL);

    // 1) pack weights + build packed im2col
    {
        long n = (long)EMB * KDIM;
        pack_weights<<<(unsigned)((n + 255) / 256), 256>>>(Wq, Wk, Wv, wqP, wkP, wvP);
        long total = (long)BATCH * NPIX * KDIM;
        build_colT<<<(unsigned)((total + 255) / 256), 256>>>(feat, colT);
    }

    const long colS = (long)NPIX * KDIM;
    const long qtS  = (long)NPIX * EMB;
    const long attS = (long)NPIX * NPIX;

    // 2) q,k conv: D[n][e] = colT[n][:] . W[e][:] + bias[e]  (packed out)
    {
        dim3 grid(EMB / 128, NPIX / 128, 2 * BATCH);
        kQK<<<grid, 256, SMEM_TOTAL>>>(colT, colS, KDIM,
                                       wqP, 0, KDIM, wkP, KDIM,
                                       nullptr, 0, 0,
                                       qT, kT, qtS, EMB,
                                       bq, bk);
    }
    // 3) v conv: D[e][n] = Wv[e][:] . colT[n][:] + bias[e]  (packed out)
    {
        dim3 grid(NPIX / 128, EMB / 128, BATCH);
        kV<<<grid, 256, SMEM_TOTAL>>>(wvP, 0, KDIM,
                                      colT, colS, KDIM, nullptr, KDIM,
                                      nullptr, 0, 0,
                                      vP, nullptr, qtS, NPIX,
                                      bv, nullptr);
    }
    // 4) logits: att[i][j] = qT[i][:] . kT[j][:]  (K=512, fp32 out)
    {
        dim3 grid(NPIX / 128, NPIX / 128, BATCH);
        kGEN<<<grid, 256, SMEM_TOTAL>>>(qT, qtS, EMB,
                                        kT, qtS, EMB, nullptr, EMB,
                                        att, attS, NPIX,
                                        nullptr, nullptr, 0, 0,
                                        nullptr, nullptr);
    }
    // 5) softmax rows + pack u32 in place
    softmax_pack<<<BATCH * NPIX, 256>>>(att);

    // 6) output: outT[i][e] = att[i][:] . vP[e][:]  (K=2304, fp32 out)
    {
        dim3 grid(EMB / 128, NPIX / 128, BATCH);
        kGEN<<<grid, 256, SMEM_TOTAL>>>((const uint32_t*)att, attS, NPIX,
                                        vP, qtS, NPIX, nullptr, NPIX,
                                        outT, qtS, EMB,
                                        nullptr, nullptr, 0, 0,
                                        nullptr, nullptr);
    }
    // 7) residual + transpose
    {
        dim3 grid(EMB / 32, NPIX / 32, BATCH);
        epilogue_kernel<<<grid, dim3(32, 8)>>>(outT, vP, out);
    }
}